// round 1
// baseline (speedup 1.0000x reference)
#include <cuda_runtime.h>

#define N_VOX   262144
#define M_PAIRS 131072
#define K_OFF   27
#define C       32

// ---------------------------------------------------------------------------
// Kernel 1: initialize out[n][c] = bias[c]  (bias add commutes with scatter)
// ---------------------------------------------------------------------------
__global__ void bias_init_kernel(float* __restrict__ out,
                                 const float* __restrict__ bias)
{
    int t = blockIdx.x * blockDim.x + threadIdx.x;
    const int total4 = N_VOX * (C / 4);      // float4 elements
    if (t < total4) {
        const float4* b4 = (const float4*)bias;   // 8 float4 of bias
        float4* o4 = (float4*)out;
        o4[t] = b4[t & 7];
    }
}

// ---------------------------------------------------------------------------
// Kernel 2: for each (k, m) pair:
//   out[out_map[k][m]][:] += input[in_map[k][m]][:] @ W[k]   (atomic scatter)
//
// One warp per pair (16 pairs per warp per launch slot). Lane = out channel.
// W[k] column `lane` is register-resident (32 regs). Input row is read with
// 8 uniform LDG.128 (warp-broadcast) so the pair loop pipelines freely.
// ---------------------------------------------------------------------------
#define WARPS_PER_BLOCK 8
#define PAIRS_PER_WARP  16

__global__ __launch_bounds__(WARPS_PER_BLOCK * 32)
void scatter_gemm_kernel(const float* __restrict__ input,
                         const float* __restrict__ kernel,
                         const int*   __restrict__ in_map,
                         const int*   __restrict__ out_map,
                         float*       __restrict__ out)
{
    const int k    = blockIdx.y;
    const int lane = threadIdx.x & 31;
    const int warp = threadIdx.x >> 5;

    // Register-resident weight column: w[i] = W[k][i][lane]
    float w[C];
    const float* Wk = kernel + k * C * C;
    #pragma unroll
    for (int i = 0; i < C; i++) w[i] = __ldg(Wk + i * C + lane);

    const int* im = in_map  + k * M_PAIRS;
    const int* om = out_map + k * M_PAIRS;

    const int base = (blockIdx.x * WARPS_PER_BLOCK + warp) * PAIRS_PER_WARP;

    #pragma unroll 4
    for (int p = 0; p < PAIRS_PER_WARP; p++) {
        const int m = base + p;
        const int irow = __ldg(im + m);
        const int orow = __ldg(om + m);

        const float4* row4 = (const float4*)(input + (size_t)irow * C);

        float acc = 0.f;
        #pragma unroll
        for (int j = 0; j < C / 4; j++) {
            float4 a = __ldg(row4 + j);          // uniform across warp -> broadcast
            acc = fmaf(a.x, w[4 * j + 0], acc);
            acc = fmaf(a.y, w[4 * j + 1], acc);
            acc = fmaf(a.z, w[4 * j + 2], acc);
            acc = fmaf(a.w, w[4 * j + 3], acc);
        }

        atomicAdd(out + (size_t)orow * C + lane, acc);   // RED.E.ADD.F32
    }
}

// ---------------------------------------------------------------------------
// Launch
// ---------------------------------------------------------------------------
extern "C" void kernel_launch(void* const* d_in, const int* in_sizes, int n_in,
                              void* d_out, int out_size)
{
    const float* input   = (const float*)d_in[0];
    const float* kernelw = (const float*)d_in[1];
    const float* bias    = (const float*)d_in[2];
    const int*   in_map  = (const int*)  d_in[3];
    const int*   out_map = (const int*)  d_in[4];
    float*       out     = (float*)d_out;

    const int total4 = N_VOX * (C / 4);
    bias_init_kernel<<<(total4 + 255) / 256, 256>>>(out, bias);

    dim3 grid(M_PAIRS / (WARPS_PER_BLOCK * PAIRS_PER_WARP), K_OFF);
    scatter_gemm_kernel<<<grid, WARPS_PER_BLOCK * 32>>>(
        input, kernelw, in_map, out_map, out);
}